// round 8
// baseline (speedup 1.0000x reference)
#include <cuda_runtime.h>
#include <cuda_bf16.h>
#include <math.h>

#define N_NODES 20000
#define N_EDGES 640000
#define FEAT    128
#define NRBF    20
#define PI_F    3.14159265358979f
#define CUTOFF  5.0f
#define CHUNK   32
#define PFD     6      // L1 prefetch depth (edges)

#define SCATTER_BLOCKS (N_EDGES / 128)          // 5000
#define GEMM_BLOCKS    (N_NODES / 16)           // 1250

typedef unsigned long long ull;

// ---------------- f32x2 packed-math helpers (Blackwell FFMA2 path) -----------
__device__ __forceinline__ ull pack2(float lo, float hi) {
    ull r; asm("mov.b64 %0, {%1, %2};" : "=l"(r) : "f"(lo), "f"(hi)); return r;
}
__device__ __forceinline__ void unpack2(ull v, float& lo, float& hi) {
    asm("mov.b64 {%0, %1}, %2;" : "=f"(lo), "=f"(hi) : "l"(v));
}
__device__ __forceinline__ ull fma2(ull a, ull b, ull c) {
    ull d; asm("fma.rn.f32x2 %0, %1, %2, %3;" : "=l"(d) : "l"(a), "l"(b), "l"(c)); return d;
}
__device__ __forceinline__ ull mul2(ull a, ull b) {
    ull d; asm("mul.rn.f32x2 %0, %1, %2;" : "=l"(d) : "l"(a), "l"(b)); return d;
}
__device__ __forceinline__ void pf_l1(const void* p) {
    asm volatile("prefetch.global.L1 [%0];" :: "l"(p));
}

// ---------------- scratch (static device allocations; no cudaMalloc) ----------
// g_count is zero at module load (static init) and re-zeroed by scan_kernel
// after each use, so the graph-replay invariant holds without a zeroing kernel.
__device__ int   g_count[N_NODES];
__device__ int   g_off[N_NODES + 1];
__device__ int   g_cursor[N_NODES];
__device__ int   g_perm[N_EDGES];
__device__ float g_phi[N_NODES * 3 * FEAT];    // 30.72 MB

// ---------------- launch 1: histogram by destination node ---------------------
// nbrs is int32 [N_EDGES, 2]: nbrs[2e] = dest node i, nbrs[2e+1] = src node j
__global__ void hist_kernel(const int* __restrict__ nbrs) {
    int e = blockIdx.x * blockDim.x + threadIdx.x;
    if (e < N_EDGES) {
        int i = nbrs[2 * e];
        atomicAdd(&g_count[i], 1);
    }
}

// ---------------- launch 2: single-block scan (+ self-clean of g_count) ------
__global__ void scan_kernel() {
    const int STRIP = 20;
    int t = threadIdx.x;
    int base = t * STRIP;
    int local[STRIP];
    int s = 0;
    #pragma unroll
    for (int u = 0; u < STRIP; ++u) {
        int idx = base + u;
        int c = 0;
        if (idx < N_NODES) { c = g_count[idx]; g_count[idx] = 0; }  // read + clean
        local[u] = s;       // exclusive within strip
        s += c;
    }
    __shared__ int sums[1024];
    sums[t] = s;
    __syncthreads();
    for (int off = 1; off < 1024; off <<= 1) {
        int v = (t >= off) ? sums[t - off] : 0;
        __syncthreads();
        sums[t] += v;
        __syncthreads();
    }
    int pre = (t > 0) ? sums[t - 1] : 0;
    #pragma unroll
    for (int u = 0; u < STRIP; ++u) {
        int idx = base + u;
        if (idx < N_NODES) {
            int o = pre + local[u];
            g_off[idx]    = o;
            g_cursor[idx] = o;
        }
    }
    if (t == 1023) g_off[N_NODES] = sums[1023];
}

// ---------------- launch 3: fused scatter + node-feature MLP ------------------
// blocks [0, SCATTER_BLOCKS): edge scatter; blocks beyond: fused GEMM
// phi = silu(s @ W1 + b1) @ W2 + b2, h kept in smem.
__global__ __launch_bounds__(128, 4)
void scatter_gemm_kernel(const int* __restrict__ nbrs,
                         const float* __restrict__ S,
                         const float* __restrict__ W1, const float* __restrict__ b1,
                         const float* __restrict__ W2, const float* __restrict__ b2) {
    if (blockIdx.x < SCATTER_BLOCKS) {
        int e = blockIdx.x * 128 + threadIdx.x;
        int i = nbrs[2 * e];
        int pos = atomicAdd(&g_cursor[i], 1);
        g_perm[pos] = e;
        return;
    }

    __shared__ float As[16][FEAT];
    __shared__ float Hs[16][FEAT];
    int row0 = (blockIdx.x - SCATTER_BLOCKS) * 16;
    int tid = threadIdx.x;
    #pragma unroll
    for (int r = 0; r < 16; ++r)
        As[r][tid] = S[(size_t)(row0 + r) * FEAT + tid];
    __syncthreads();

    {
        float acc[16];
        #pragma unroll
        for (int r = 0; r < 16; ++r) acc[r] = 0.f;
        #pragma unroll 4
        for (int k = 0; k < FEAT; ++k) {
            float b = W1[k * FEAT + tid];
            #pragma unroll
            for (int r = 0; r < 16; ++r) acc[r] = fmaf(As[r][k], b, acc[r]);
        }
        float bias = b1[tid];
        #pragma unroll
        for (int r = 0; r < 16; ++r) {
            float x = acc[r] + bias;
            Hs[r][tid] = x / (1.f + expf(-x));   // silu
        }
    }
    __syncthreads();

    float a0[16], a1[16], a2[16];
    #pragma unroll
    for (int r = 0; r < 16; ++r) { a0[r] = 0.f; a1[r] = 0.f; a2[r] = 0.f; }

    #pragma unroll 2
    for (int k = 0; k < FEAT; ++k) {
        const float* wrow = W2 + (size_t)k * 384;
        float b0 = wrow[tid];
        float b1v = wrow[128 + tid];
        float b2v = wrow[256 + tid];
        #pragma unroll
        for (int r = 0; r < 16; ++r) {
            float h = Hs[r][k];
            a0[r] = fmaf(h, b0, a0[r]);
            a1[r] = fmaf(h, b1v, a1[r]);
            a2[r] = fmaf(h, b2v, a2[r]);
        }
    }
    float bb0 = b2[tid], bb1 = b2[128 + tid], bb2 = b2[256 + tid];
    #pragma unroll
    for (int r = 0; r < 16; ++r) {
        float* prow = g_phi + (size_t)(row0 + r) * 384;
        prow[tid]       = a0[r] + bb0;
        prow[128 + tid] = a1[r] + bb1;
        prow[256 + tid] = a2[r] + bb2;
    }
}

// ---------------- launch 4 (ncu-sampled slot): per-node message + aggregation -
// One CTA (64 threads) per destination node i; edges processed in PAIRS.
// Thread t owns feature columns (2t, 2t+1) of each of the 3 splits.
// s_rbf2 is transposed [k][t] so one LDS.128 serves two edges.
__global__ __launch_bounds__(64, 5)
void node_kernel(const int* __restrict__ nbrs,
                 const float* __restrict__ r_ij,
                 const float* __restrict__ v_j,
                 const float* __restrict__ Wd,
                 const float* __restrict__ bd,
                 float* __restrict__ out) {
    int i   = blockIdx.x;
    int tid = threadIdx.x;          // 0..63
    int f2  = 2 * tid;              // first of this thread's feature pair
    int start = g_off[i];
    int end   = g_off[i + 1];

    // Wd column-pairs in registers; slot 20 = bd (paired with env as 21st rbf)
    ull wd0[NRBF + 1], wd1[NRBF + 1], wd2[NRBF + 1];
    #pragma unroll
    for (int k = 0; k < NRBF; ++k) {
        const float* wrow = Wd + (size_t)k * 384;
        wd0[k] = *(const ull*)(wrow + f2);
        wd1[k] = *(const ull*)(wrow + 128 + f2);
        wd2[k] = *(const ull*)(wrow + 256 + f2);
    }
    wd0[NRBF] = *(const ull*)(bd + f2);
    wd1[NRBF] = *(const ull*)(bd + 128 + f2);
    wd2[NRBF] = *(const ull*)(bd + 256 + f2);

    ull acc_s = 0ull, av0 = 0ull, av1 = 0ull, av2 = 0ull;  // 0.0f pairs

    __shared__ ull s_rbf2[NRBF + 1][CHUNK];  // TRANSPOSED: [k][t]; [20][t] = env dup
    __shared__ ull s_u[CHUNK][3];            // unit vector components, duplicated
    __shared__ int s_j[CHUNK];

    for (int base = start; base < end; base += CHUNK) {
        int n = min(CHUNK, end - base);
        __syncthreads();  // protect smem from previous iteration's readers

        if (tid < n) {
            int e = g_perm[base + tid];
            s_j[tid] = nbrs[2 * e + 1];
            const float* rp = r_ij + 3 * (size_t)e;
            float x = rp[0], y = rp[1], z = rp[2];
            float d = sqrtf(fmaf(x, x, fmaf(y, y, fmaf(z, z, 3e-15f))));
            float invd = 1.f / d;
            s_u[tid][0] = pack2(x * invd, x * invd);
            s_u[tid][1] = pack2(y * invd, y * invd);
            s_u[tid][2] = pack2(z * invd, z * invd);
            // one fast sincos; envelope reuses cos; rbf via Chebyshev recurrence.
            // Contributing edges have theta < pi (MUFU-accurate); d >= CUTOFF zeroed by env.
            float theta = d * (PI_F / CUTOFF);
            float st, ct;
            __sincosf(theta, &st, &ct);
            float env = (d < CUTOFF) ? 0.5f * (ct + 1.f) : 0.f;
            s_rbf2[NRBF][tid] = pack2(env, env);
            float sc = env * invd;
            float c2  = 2.f * ct;
            float skm = 0.f;   // sin(0*theta)
            float sk  = st;    // sin(1*theta)
            #pragma unroll
            for (int k = 0; k < NRBF; ++k) {
                float r = sk * sc;
                s_rbf2[k][tid] = pack2(r, r);
                float nx = fmaf(c2, sk, -skm);
                skm = sk; sk = nx;
            }
        }
        __syncthreads();

        // warm-up L1 prefetch
        int npf = min(PFD, n);
        for (int t0 = 0; t0 < npf; ++t0) {
            int jp = s_j[t0];
            const float* pp = g_phi + (size_t)jp * 384;
            pf_l1(pp + f2);
            pf_l1(pp + 128 + f2);
            pf_l1(pp + 256 + f2);
            pf_l1(v_j + (size_t)jp * 384 + 3 * (size_t)f2);
        }

        int t = 0;
        for (; t + 1 < n; t += 2) {
            // steady-state prefetch for the pair PFD ahead
            if (t + PFD < n) {
                int jp = s_j[t + PFD];
                const float* pp = g_phi + (size_t)jp * 384;
                pf_l1(pp + f2);
                pf_l1(pp + 128 + f2);
                pf_l1(pp + 256 + f2);
                pf_l1(v_j + (size_t)jp * 384 + 3 * (size_t)f2);
            }
            if (t + 1 + PFD < n) {
                int jp = s_j[t + 1 + PFD];
                const float* pp = g_phi + (size_t)jp * 384;
                pf_l1(pp + f2);
                pf_l1(pp + 128 + f2);
                pf_l1(pp + 256 + f2);
                pf_l1(v_j + (size_t)jp * 384 + 3 * (size_t)f2);
            }

            int ja = s_j[t], jb = s_j[t + 1];
            const float* prA = g_phi + (size_t)ja * 384;
            const float* prB = g_phi + (size_t)jb * 384;
            ull p0a = *(const ull*)(prA + f2);
            ull p1a = *(const ull*)(prA + 128 + f2);
            ull p2a = *(const ull*)(prA + 256 + f2);
            ull p0b = *(const ull*)(prB + f2);
            ull p1b = *(const ull*)(prB + 128 + f2);
            ull p2b = *(const ull*)(prB + 256 + f2);
            const float2* vrA = (const float2*)(v_j + (size_t)ja * 384 + 3 * (size_t)f2);
            const float2* vrB = (const float2*)(v_j + (size_t)jb * 384 + 3 * (size_t)f2);
            float2 vaa = vrA[0], vba = vrA[1], vca = vrA[2];
            float2 vab = vrB[0], vbb = vrB[1], vcb = vrB[2];

            // 6 independent fma chains; one LDS.128 per k serves both edges
            ull ws0a = 0ull, ws1a = 0ull, ws2a = 0ull;
            ull ws0b = 0ull, ws1b = 0ull, ws2b = 0ull;
            #pragma unroll
            for (int k = 0; k <= NRBF; ++k) {
                ulonglong2 rr = *(const ulonglong2*)&s_rbf2[k][t];  // LDS.128
                ws0a = fma2(rr.x, wd0[k], ws0a);
                ws1a = fma2(rr.x, wd1[k], ws1a);
                ws2a = fma2(rr.x, wd2[k], ws2a);
                ws0b = fma2(rr.y, wd0[k], ws0b);
                ws1b = fma2(rr.y, wd1[k], ws1b);
                ws2b = fma2(rr.y, wd2[k], ws2b);
            }

            // edge a
            ull vx = pack2(vaa.x, vba.y);
            ull vy = pack2(vaa.y, vca.x);
            ull vz = pack2(vba.x, vca.y);
            ull i0 = mul2(p0a, ws0a);
            ull i2 = mul2(p2a, ws2a);
            acc_s = fma2(p1a, ws1a, acc_s);
            av0 = fma2(i0, vx, av0); av0 = fma2(i2, s_u[t][0], av0);
            av1 = fma2(i0, vy, av1); av1 = fma2(i2, s_u[t][1], av1);
            av2 = fma2(i0, vz, av2); av2 = fma2(i2, s_u[t][2], av2);

            // edge b
            vx = pack2(vab.x, vbb.y);
            vy = pack2(vab.y, vcb.x);
            vz = pack2(vbb.x, vcb.y);
            i0 = mul2(p0b, ws0b);
            i2 = mul2(p2b, ws2b);
            acc_s = fma2(p1b, ws1b, acc_s);
            av0 = fma2(i0, vx, av0); av0 = fma2(i2, s_u[t + 1][0], av0);
            av1 = fma2(i0, vy, av1); av1 = fma2(i2, s_u[t + 1][1], av1);
            av2 = fma2(i0, vz, av2); av2 = fma2(i2, s_u[t + 1][2], av2);
        }

        if (t < n) {  // odd tail
            int j = s_j[t];
            const float* prow = g_phi + (size_t)j * 384;
            ull p0 = *(const ull*)(prow + f2);
            ull p1 = *(const ull*)(prow + 128 + f2);
            ull p2 = *(const ull*)(prow + 256 + f2);
            const float2* vrow = (const float2*)(v_j + (size_t)j * 384 + 3 * (size_t)f2);
            float2 va = vrow[0], vb = vrow[1], vc = vrow[2];

            ull ws0 = 0ull, ws1 = 0ull, ws2 = 0ull;
            #pragma unroll
            for (int k = 0; k <= NRBF; ++k) {
                ull rr = s_rbf2[k][t];
                ws0 = fma2(rr, wd0[k], ws0);
                ws1 = fma2(rr, wd1[k], ws1);
                ws2 = fma2(rr, wd2[k], ws2);
            }
            ull vx = pack2(va.x, vb.y);
            ull vy = pack2(va.y, vc.x);
            ull vz = pack2(vb.x, vc.y);
            ull i0 = mul2(p0, ws0);
            ull i2 = mul2(p2, ws2);
            acc_s = fma2(p1, ws1, acc_s);
            av0 = fma2(i0, vx, av0); av0 = fma2(i2, s_u[t][0], av0);
            av1 = fma2(i0, vy, av1); av1 = fma2(i2, s_u[t][1], av1);
            av2 = fma2(i0, vz, av2); av2 = fma2(i2, s_u[t][2], av2);
        }
    }

    // outputs: delta_s [N,128] then delta_v [N,128,3]
    float slo, shi;
    unpack2(acc_s, slo, shi);
    out[(size_t)i * FEAT + f2]     = slo;
    out[(size_t)i * FEAT + f2 + 1] = shi;

    float a0l, a0h, a1l, a1h, a2l, a2h;
    unpack2(av0, a0l, a0h);
    unpack2(av1, a1l, a1h);
    unpack2(av2, a2l, a2h);
    float* vout = out + (size_t)N_NODES * FEAT + ((size_t)i * FEAT + f2) * 3;
    vout[0] = a0l; vout[1] = a1l; vout[2] = a2l;
    vout[3] = a0h; vout[4] = a1h; vout[5] = a2h;
}

// ---------------- launch ------------------------------------------------------
extern "C" void kernel_launch(void* const* d_in, const int* in_sizes, int n_in,
                              void* d_out, int out_size) {
    const float* s_j  = (const float*)d_in[0];
    const float* v_j  = (const float*)d_in[1];
    const float* r_ij = (const float*)d_in[2];
    const int*   nbrs = (const int*)d_in[3];     // int32 (JAX x64 disabled)
    const float* W1   = (const float*)d_in[4];
    const float* b1   = (const float*)d_in[5];
    const float* W2   = (const float*)d_in[6];
    const float* b2   = (const float*)d_in[7];
    const float* Wd   = (const float*)d_in[8];
    const float* bd   = (const float*)d_in[9];
    float* out = (float*)d_out;

    hist_kernel<<<N_EDGES / 256, 256>>>(nbrs);                       // launch 1
    scan_kernel<<<1, 1024>>>();                                      // launch 2
    scatter_gemm_kernel<<<SCATTER_BLOCKS + GEMM_BLOCKS, 128>>>(      // launch 3
        nbrs, s_j, W1, b1, W2, b2);
    node_kernel<<<N_NODES, 64>>>(nbrs, r_ij, v_j, Wd, bd, out);      // launch 4
}